// round 5
// baseline (speedup 1.0000x reference)
#include <cuda_runtime.h>

#define NB 8
#define SS 512
#define EE 128
#define DD 512
#define NVOCAB 32000
#define STILE 16

// scratch: m[b][o][i]  (8 * 512 * 128 floats = 2 MB)
__device__ float g_m[NB * DD * EE];

static __device__ __forceinline__ unsigned long long pack2(float lo, float hi) {
    unsigned long long r;
    asm("mov.b64 %0, {%1, %2};" : "=l"(r) : "f"(lo), "f"(hi));
    return r;
}
static __device__ __forceinline__ void unpack2(unsigned long long v, float &lo, float &hi) {
    asm("mov.b64 {%0, %1}, %2;" : "=f"(lo), "=f"(hi) : "l"(v));
}
static __device__ __forceinline__ unsigned long long fma2(unsigned long long a,
                                                          unsigned long long b,
                                                          unsigned long long c) {
    unsigned long long d;
    asm("fma.rn.f32x2 %0, %1, %2, %3;" : "=l"(d) : "l"(a), "l"(b), "l"(c));
    return d;
}
static __device__ __forceinline__ float comp4(float4 v, int t) {
    return t == 0 ? v.x : (t == 1 ? v.y : (t == 2 ? v.z : v.w));
}

// K1: m[b,o,i] = sum_j W[o,i,j] * king_tab[king_id[b], j]
// grid 256 blocks x 256 threads: each block handles 2 o-rows (o = 2*bid + tid>>7),
// thread lane i = tid & 127. W (32MB) streamed exactly once from HBM; 256-thread
// blocks give ~28 warps/SM so in-flight bytes (~28KB/SM) exceed the ~23KB needed
// to saturate the ~6300 B/cyc LTS cap. All 8 batches accumulated as 4 f32x2 regs.
__global__ __launch_bounds__(256) void k1_project(const float* __restrict__ W,
                                                  const float* __restrict__ ktab,
                                                  const int* __restrict__ kid) {
    __shared__ __align__(16) float2 kp[EE][4];  // kp[j][bp] = (king[2bp][j], king[2bp+1][j])
    const int i = threadIdx.x & 127;
    const int o = blockIdx.x * 2 + (threadIdx.x >> 7);
    if (threadIdx.x < 128) {
#pragma unroll
        for (int bp = 0; bp < 4; bp++) {
            int kb0 = kid[2 * bp], kb1 = kid[2 * bp + 1];
            kp[i][bp] = make_float2(ktab[kb0 * EE + i], ktab[kb1 * EE + i]);
        }
    }
    __syncthreads();

    const float4* wrow = (const float4*)(W + ((long)o * EE + i) * EE);
    unsigned long long acc0 = 0, acc1 = 0, acc2 = 0, acc3 = 0;
#pragma unroll 8
    for (int jc = 0; jc < 32; jc++) {
        float4 w = wrow[jc];
#pragma unroll
        for (int t = 0; t < 4; t++) {
            float wv = comp4(w, t);
            unsigned long long wp = pack2(wv, wv);
            const ulonglong2* kj = (const ulonglong2*)&kp[jc * 4 + t][0];
            ulonglong2 q01 = kj[0];
            ulonglong2 q23 = kj[1];
            acc0 = fma2(wp, q01.x, acc0);
            acc1 = fma2(wp, q01.y, acc1);
            acc2 = fma2(wp, q23.x, acc2);
            acc3 = fma2(wp, q23.y, acc3);
        }
    }
    long oi = (long)o * EE + i;
    float lo, hi;
    unpack2(acc0, lo, hi); g_m[0L * DD * EE + oi] = lo; g_m[1L * DD * EE + oi] = hi;
    unpack2(acc1, lo, hi); g_m[2L * DD * EE + oi] = lo; g_m[3L * DD * EE + oi] = hi;
    unpack2(acc2, lo, hi); g_m[4L * DD * EE + oi] = lo; g_m[5L * DD * EE + oi] = hi;
    unpack2(acc3, lo, hi); g_m[6L * DD * EE + oi] = lo; g_m[7L * DD * EE + oi] = hi;
}

// inner K2 step for one kc: 2 LDS.128 rows (broadcast, swizzle-compensated) and
// 16 FFMA2. KEY = kc&3 (compile-time in both call sites).
#define K2_STEP(W0, W1, KEY, KC)                                                   \
    do {                                                                           \
        _Pragma("unroll") for (int t = 0; t < 4; t++) {                            \
            float a0 = comp4((W0), t);                                             \
            float a1 = comp4((W1), t);                                             \
            unsigned long long mp0 = pack2(a0, a0);                                \
            unsigned long long mp1 = pack2(a1, a1);                                \
            const ulonglong2* ar = (const ulonglong2*)&At2f[(KC)*4 + t][0];        \
            ulonglong2 p[4];                                                       \
            _Pragma("unroll") for (int g = 0; g < 4; g++) p[g] = ar[g ^ (KEY)];    \
            _Pragma("unroll") for (int g = 0; g < 4; g++) {                        \
                acc[2 * g + 0][0] = fma2(p[g].x, mp0, acc[2 * g + 0][0]);          \
                acc[2 * g + 0][1] = fma2(p[g].x, mp1, acc[2 * g + 0][1]);          \
                acc[2 * g + 1][0] = fma2(p[g].y, mp0, acc[2 * g + 1][0]);          \
                acc[2 * g + 1][1] = fma2(p[g].y, mp1, acc[2 * g + 1][1]);          \
            }                                                                      \
        }                                                                          \
    } while (0)

// K2: fused gather + GEMM (x[s,o] = sum_i A[s,i]*m[o,i] + bias[o]) + LayerNorm.
// grid = B * S/STILE = 256 blocks, 256 threads.
// Thread t owns output columns o = 2t, 2t+1 for all 16 s-rows of the tile:
// 16 f32x2 accumulators, each holding an (s,s+1) pair for one o.
//
// A-tile layout: At2f[k] is a 64B row holding 4 pair-groups (each 16B =
// two float2 s-pairs). Pair-group slots are XOR-swizzled by (k>>2)&3 so the
// gather's stores (k-stride 4 per lane) spread over 4 bank groups (8-way)
// instead of one bank (32-way). The compute loop reads the full row
// broadcast via LDS.128 at slot g ^ (kc&3) with immediate offsets.
// The first m row (kc=0) and the bias are prefetched BEFORE __syncthreads so
// their L2 latency hides under the barrier instead of stalling the loop head
// (ptxas will not hoist LDG across BAR.SYNC itself).
__global__ __launch_bounds__(256) void k2_gemm_ln(const float* __restrict__ emb,
                                                 const int* __restrict__ seq,
                                                 const int* __restrict__ kid,
                                                 const float* __restrict__ bias,
                                                 const float* __restrict__ gamma,
                                                 const float* __restrict__ beta,
                                                 float* __restrict__ out) {
    __shared__ __align__(16) float At2f[EE][16];    // 8 KB, swizzled A^T pairs
    __shared__ __align__(16) float xbuf[STILE][DD]; // 32 KB

    const int tid = threadIdx.x;
    const int b = blockIdx.x >> 5;
    const int st = blockIdx.x & 31;
    const int s0 = st * STILE;
    const int king = kid[b];

    // gather: warp sp (= tid>>5) loads token rows 2sp and 2sp+1 (each a fully
    // coalesced 512B row across lanes q) and writes transposed float2 pairs.
    {
        const int sp = tid >> 5, q = tid & 31;
        int tok0 = seq[b * SS + s0 + 2 * sp];
        int tok1 = seq[b * SS + s0 + 2 * sp + 1];
        float4 v0 = ((const float4*)(emb + ((long)king * NVOCAB + tok0) * EE))[q];
        float4 v1 = ((const float4*)(emb + ((long)king * NVOCAB + tok1) * EE))[q];
        int off = (((sp >> 1) ^ (q & 3)) << 2) + ((sp & 1) << 1);
        *(float2*)&At2f[4 * q + 0][off] = make_float2(v0.x, v1.x);
        *(float2*)&At2f[4 * q + 1][off] = make_float2(v0.y, v1.y);
        *(float2*)&At2f[4 * q + 2][off] = make_float2(v0.z, v1.z);
        *(float2*)&At2f[4 * q + 3][off] = make_float2(v0.w, v1.w);
    }

    const int o0 = tid * 2;
    const float4* m0 = (const float4*)(g_m + ((long)b * DD + o0) * EE);
    const float4* m1 = m0 + EE / 4;

    // prefetch first m row + bias before the barrier (latency hides under BAR)
    const float4 pre0 = m0[0];
    const float4 pre1 = m1[0];
    const float bb0 = bias[o0], bb1 = bias[o0 + 1];

    // accumulators pre-seeded with bias (both s-halves get the same o-bias)
    unsigned long long binit0 = pack2(bb0, bb0);
    unsigned long long binit1 = pack2(bb1, bb1);
    unsigned long long acc[8][2];
#pragma unroll
    for (int sp = 0; sp < 8; sp++) { acc[sp][0] = binit0; acc[sp][1] = binit1; }

    __syncthreads();

    // peeled kc = 0 consumes the prefetched m row
    K2_STEP(pre0, pre1, 0, 0);

#pragma unroll 4
    for (int kc = 1; kc < 32; kc++) {
        float4 w0 = m0[kc];
        float4 w1 = m1[kc];
        int key = kc & 3;  // compile-time per unroll replica (start 1, step 1)
        K2_STEP(w0, w1, key, kc);
    }

    // deposit into xbuf as float2 of adjacent columns (o0, o0+1)
#pragma unroll
    for (int sp = 0; sp < 8; sp++) {
        float l0, h0, l1, h1;
        unpack2(acc[sp][0], l0, h0);
        unpack2(acc[sp][1], l1, h1);
        *(float2*)&xbuf[2 * sp + 0][o0] = make_float2(l0, l1);
        *(float2*)&xbuf[2 * sp + 1][o0] = make_float2(h0, h1);
    }
    __syncthreads();

    // LayerNorm: warp per 2 rows; lane covers 16 elements as 4 float4s
    const int w = tid >> 5, lane = tid & 31;
    for (int s = w; s < STILE; s += 8) {
        float4 v[4];
        float sum = 0.f, sq = 0.f;
#pragma unroll
        for (int u = 0; u < 4; u++) {
            v[u] = *(const float4*)&xbuf[s][lane * 4 + 128 * u];
            sum += v[u].x + v[u].y + v[u].z + v[u].w;
            sq += v[u].x * v[u].x + v[u].y * v[u].y + v[u].z * v[u].z + v[u].w * v[u].w;
        }
#pragma unroll
        for (int off = 16; off > 0; off >>= 1) {
            sum += __shfl_xor_sync(0xffffffffu, sum, off);
            sq += __shfl_xor_sync(0xffffffffu, sq, off);
        }
        float mean = sum * (1.0f / DD);
        float var = sq * (1.0f / DD) - mean * mean;
        float rstd = rsqrtf(var + 1e-5f);
        float* orow = out + ((long)blockIdx.x * STILE + s) * DD;
#pragma unroll
        for (int u = 0; u < 4; u++) {
            int o = lane * 4 + 128 * u;
            float4 g = *(const float4*)&gamma[o];
            float4 be = *(const float4*)&beta[o];
            float4 r;
            r.x = (v[u].x - mean) * rstd * g.x + be.x;
            r.y = (v[u].y - mean) * rstd * g.y + be.y;
            r.z = (v[u].z - mean) * rstd * g.z + be.z;
            r.w = (v[u].w - mean) * rstd * g.w + be.w;
            *(float4*)&orow[o] = r;
        }
    }
}

extern "C" void kernel_launch(void* const* d_in, const int* in_sizes, int n_in,
                              void* d_out, int out_size) {
    const int* seq = (const int*)d_in[0];
    const int* kid = (const int*)d_in[1];
    const float* emb = (const float*)d_in[2];
    const float* ktab = (const float*)d_in[3];
    const float* W = (const float*)d_in[4];
    const float* bias = (const float*)d_in[5];
    const float* gamma = (const float*)d_in[6];
    const float* beta = (const float*)d_in[7];
    float* out = (float*)d_out;

    k1_project<<<DD / 2, 256>>>(W, ktab, kid);
    k2_gemm_ln<<<NB * (SS / STILE), 256>>>(emb, seq, kid, bias, gamma, beta, out);
}

// round 6
// speedup vs baseline: 1.3681x; 1.3681x over previous
#include <cuda_runtime.h>

#define NB 8
#define SS 512
#define EE 128
#define DD 512
#define VOCABN 32000
#define STILE 32

// scratch: mT[b][i][o]  (transposed so K2's m loads are coalesced over o)
__device__ float g_mT[(long)NB * EE * DD];

static __device__ __forceinline__ unsigned long long pack2(float lo, float hi) {
    unsigned long long r;
    asm("mov.b64 %0, {%1, %2};" : "=l"(r) : "f"(lo), "f"(hi));
    return r;
}
static __device__ __forceinline__ void unpack2(unsigned long long v, float &lo, float &hi) {
    asm("mov.b64 {%0, %1}, %2;" : "=f"(lo), "=f"(hi) : "l"(v));
}
static __device__ __forceinline__ unsigned long long fma2(unsigned long long a,
                                                          unsigned long long b,
                                                          unsigned long long c) {
    unsigned long long d;
    asm("fma.rn.f32x2 %0, %1, %2, %3;" : "=l"(d) : "l"(a), "l"(b), "l"(c));
    return d;
}
static __device__ __forceinline__ unsigned long long add2(unsigned long long a,
                                                          unsigned long long b) {
    unsigned long long d;
    asm("add.rn.f32x2 %0, %1, %2;" : "=l"(d) : "l"(a), "l"(b));
    return d;
}
static __device__ __forceinline__ float comp4(float4 v, int t) {
    return t == 0 ? v.x : (t == 1 ? v.y : (t == 2 ? v.z : v.w));
}

// K1: mT[b][i][o] = sum_j W[o,i,j] * king[b][j]
// grid 256 x 128 threads. Thread owns 2 cells (o, i0) and (o, i0+1); lanes are
// consecutive in o so the mT store is coalesced. King reads amortized over both
// cells: 0.5 float/FMA of smem delivery (was 1.0) -> crossbar ~= HBM floor.
__global__ __launch_bounds__(128) void k1_project(const float* __restrict__ W,
                                                  const float* __restrict__ ktab,
                                                  const int* __restrict__ kid) {
    __shared__ __align__(16) float2 kp[EE][4];  // kp[j][bp] = (king[2bp][j], king[2bp+1][j])
    const int tid = threadIdx.x;
    const int o = ((blockIdx.x & 3) << 7) + tid;      // 4 o-chunks of 128
    const int i0 = (blockIdx.x >> 2) << 1;            // 64 i-pairs
#pragma unroll
    for (int bp = 0; bp < 4; bp++) {
        int kb0 = kid[2 * bp], kb1 = kid[2 * bp + 1];
        kp[tid][bp] = make_float2(ktab[kb0 * EE + tid], ktab[kb1 * EE + tid]);
    }
    __syncthreads();

    const float4* w0 = (const float4*)(W + ((long)o * EE + i0) * EE);
    const float4* w1 = w0 + (EE / 4);

    unsigned long long accA[4] = {0, 0, 0, 0};
    unsigned long long accB[4] = {0, 0, 0, 0};
#pragma unroll 4
    for (int jc = 0; jc < 32; jc++) {
        float4 a = w0[jc];
        float4 b = w1[jc];
#pragma unroll
        for (int t = 0; t < 4; t++) {
            const ulonglong2* kj = (const ulonglong2*)&kp[4 * jc + t][0];
            ulonglong2 k01 = kj[0];
            ulonglong2 k23 = kj[1];
            float av = comp4(a, t), bv = comp4(b, t);
            unsigned long long wa = pack2(av, av);
            unsigned long long wb = pack2(bv, bv);
            accA[0] = fma2(wa, k01.x, accA[0]);
            accA[1] = fma2(wa, k01.y, accA[1]);
            accA[2] = fma2(wa, k23.x, accA[2]);
            accA[3] = fma2(wa, k23.y, accA[3]);
            accB[0] = fma2(wb, k01.x, accB[0]);
            accB[1] = fma2(wb, k01.y, accB[1]);
            accB[2] = fma2(wb, k23.x, accB[2]);
            accB[3] = fma2(wb, k23.y, accB[3]);
        }
    }
    // coalesced stores: lanes consecutive in o
#pragma unroll
    for (int p = 0; p < 4; p++) {
        float lo, hi;
        unpack2(accA[p], lo, hi);
        g_mT[((long)(2 * p) * EE + i0) * DD + o] = lo;
        g_mT[((long)(2 * p + 1) * EE + i0) * DD + o] = hi;
        unpack2(accB[p], lo, hi);
        g_mT[((long)(2 * p) * EE + i0 + 1) * DD + o] = lo;
        g_mT[((long)(2 * p + 1) * EE + i0 + 1) * DD + o] = hi;
    }
}

// ---- K2 helpers (macros so key stays compile-time per unroll replica) ----

// prefetch kc's 4 k-rows of mT (8 o-floats each) into BUF[8] float4s
#define K2_PREF(BUF, KC)                                                    \
    do {                                                                    \
        _Pragma("unroll") for (int t = 0; t < 4; t++) {                     \
            (BUF)[2 * t] = mtb[(4 * (KC) + t) * (DD / 4) + 2 * og];         \
            (BUF)[2 * t + 1] = mtb[(4 * (KC) + t) * (DD / 4) + 2 * og + 1]; \
        }                                                                   \
    } while (0)

// compute kc's 4 k-steps: per k, 2 broadcast LDS.128 (4 swizzled s-pairs) and
// 8 m-scalars from BUF -> 32 FFMA2
#define K2_COMP(BUF, KC)                                                    \
    do {                                                                    \
        const int key_ = (KC) & 3;                                          \
        _Pragma("unroll") for (int t = 0; t < 4; t++) {                     \
            const ulonglong2* ap =                                          \
                (const ulonglong2*)&At2f[4 * (KC) + t][8 * sg];             \
            ulonglong2 aL = ap[0], aH = ap[1];                              \
            unsigned long long p4[4] = {aL.x, aL.y, aH.x, aH.y};            \
            unsigned long long A0 = p4[0 ^ key_];                           \
            unsigned long long A1 = p4[1 ^ key_];                           \
            unsigned long long A2 = p4[2 ^ key_];                           \
            unsigned long long A3 = p4[3 ^ key_];                           \
            float4 mlo = (BUF)[2 * t], mhi = (BUF)[2 * t + 1];              \
            _Pragma("unroll") for (int oo = 0; oo < 8; oo++) {              \
                float mv = comp4(oo < 4 ? mlo : mhi, oo & 3);               \
                unsigned long long mp = pack2(mv, mv);                      \
                acc[0][oo] = fma2(A0, mp, acc[0][oo]);                      \
                acc[1][oo] = fma2(A1, mp, acc[1][oo]);                      \
                acc[2][oo] = fma2(A2, mp, acc[2][oo]);                      \
                acc[3][oo] = fma2(A3, mp, acc[3][oo]);                      \
            }                                                               \
        }                                                                   \
    } while (0)

// K2: fused gather + GEMM + in-register LayerNorm.
// grid = B * S/32 = 128 blocks (one wave), 256 threads.
// Thread (sg = tid>>6, og = tid&63) owns 8 s-rows (4 f32x2 pairs) x 8 o-cols:
// 32 f32x2 accumulators. Per-thread operand traffic = 0.25 float/FMA, so the
// L1TEX time (~16K cyc) matches the FFMA2 pipe time (~16K cyc) instead of
// dominating it 2:1 as in the 16s x 2o tiling.
// A tile: At2f[k] = 128B row of 16 float2 s-pairs; pair slots XOR-swizzled by
// (k>>2)&3 within groups of 4 so gather stores spread banks; compute reads the
// 4 pairs of its s-group as 2 broadcast LDS.128 with compile-time permutation.
__global__ __launch_bounds__(256, 1) void k2_gemm_ln(const float* __restrict__ emb,
                                                     const int* __restrict__ seq,
                                                     const int* __restrict__ kid,
                                                     const float* __restrict__ bias,
                                                     const float* __restrict__ gamma,
                                                     const float* __restrict__ beta,
                                                     float* __restrict__ out) {
    __shared__ __align__(16) float At2f[EE][32];        // 16 KB
    __shared__ unsigned long long red[8][8];            // cross-warp LN partials

    const int tid = threadIdx.x;
    const int b = blockIdx.x >> 4;
    const int st = blockIdx.x & 15;
    const int s0 = st * STILE;
    const int king = kid[b];
    const int sg = tid >> 6;        // s-group: rows 8sg..8sg+7
    const int og = tid & 63;        // o-group: cols 8og..8og+7
    const int o0 = og << 3;

    // gather: warp w owns s-pairs 2w, 2w+1 (s = 4w..4w+3); lane q loads col-chunk q
    {
        const int w = tid >> 5, q = tid & 31;
        const int sb = s0 + 4 * w;
        int t0 = seq[b * SS + sb + 0];
        int t1 = seq[b * SS + sb + 1];
        int t2 = seq[b * SS + sb + 2];
        int t3 = seq[b * SS + sb + 3];
        float4 v0 = ((const float4*)(emb + ((long)king * VOCABN + t0) * EE))[q];
        float4 v1 = ((const float4*)(emb + ((long)king * VOCABN + t1) * EE))[q];
        float4 v2 = ((const float4*)(emb + ((long)king * VOCABN + t2) * EE))[q];
        float4 v3 = ((const float4*)(emb + ((long)king * VOCABN + t3) * EE))[q];
        const int g4 = (2 * w) & ~3;      // slot group base
        const int d0 = (2 * w) & 3;       // 0 or 2
        const int kx = q & 3;             // swizzle key (= (k>>2)&3 since k = 4q+c)
#pragma unroll
        for (int c = 0; c < 4; c++) {
            int k = 4 * q + c;
            int ph0 = g4 + (d0 ^ kx);
            int ph1 = g4 + ((d0 + 1) ^ kx);
            *(float2*)&At2f[k][2 * ph0] = make_float2(comp4(v0, c), comp4(v1, c));
            *(float2*)&At2f[k][2 * ph1] = make_float2(comp4(v2, c), comp4(v3, c));
        }
    }

    const float4* mtb = (const float4*)(g_mT + (long)b * EE * DD);

    // prefetch kc=0's m before the barrier (hides L2 latency under BAR)
    float4 buf0[8], buf1[8];
    K2_PREF(buf0, 0);

    // bias-seeded accumulators: acc[d][oo] = f32x2 over (s_even, s_odd) for o = o0+oo
    float4 bb0 = ((const float4*)(bias + o0))[0];
    float4 bb1 = ((const float4*)(bias + o0))[1];
    unsigned long long acc[4][8];
#pragma unroll
    for (int oo = 0; oo < 8; oo++) {
        float bv = comp4(oo < 4 ? bb0 : bb1, oo & 3);
        unsigned long long bp = pack2(bv, bv);
        acc[0][oo] = bp; acc[1][oo] = bp; acc[2][oo] = bp; acc[3][oo] = bp;
    }
    __syncthreads();

    // ping-pong mainloop: kc replicas are 0,2 (mod 4) so all keys compile-time
#pragma unroll 2
    for (int kc = 0; kc < 32; kc += 2) {
        K2_PREF(buf1, kc + 1);
        K2_COMP(buf0, kc);
        int nk = (kc + 2 < 32) ? (kc + 2) : 0;  // clamped dummy prefetch on last iter
        K2_PREF(buf0, nk);
        K2_COMP(buf1, kc + 1);
    }

    // ---- LayerNorm, fully in registers + 512B smem ----
    // per-thread partial sums over this thread's 8 o, kept as f32x2 (even s, odd s)
    unsigned long long sum2[4], sq2[4];
#pragma unroll
    for (int d = 0; d < 4; d++) {
        sum2[d] = 0ULL; sq2[d] = 0ULL;
#pragma unroll
        for (int oo = 0; oo < 8; oo++) {
            sum2[d] = add2(sum2[d], acc[d][oo]);
            sq2[d] = fma2(acc[d][oo], acc[d][oo], sq2[d]);
        }
    }
    // warp reduce (lanes of a warp are 32 consecutive og, same sg)
#pragma unroll
    for (int off = 16; off > 0; off >>= 1) {
#pragma unroll
        for (int d = 0; d < 4; d++) {
            sum2[d] = add2(sum2[d], __shfl_xor_sync(0xffffffffu, sum2[d], off));
            sq2[d] = add2(sq2[d], __shfl_xor_sync(0xffffffffu, sq2[d], off));
        }
    }
    // cross-warp combine (two warps share each sg)
    const int w = tid >> 5, lane = tid & 31;
    if (lane == 0) {
#pragma unroll
        for (int d = 0; d < 4; d++) { red[w][d] = sum2[d]; red[w][4 + d] = sq2[d]; }
    }
    __syncthreads();
    const int pw = w ^ 1;
#pragma unroll
    for (int d = 0; d < 4; d++) {
        sum2[d] = add2(sum2[d], red[pw][d]);
        sq2[d] = add2(sq2[d], red[pw][4 + d]);
    }

    float4 g0 = ((const float4*)(gamma + o0))[0];
    float4 g1 = ((const float4*)(gamma + o0))[1];
    float4 e0 = ((const float4*)(beta + o0))[0];
    float4 e1 = ((const float4*)(beta + o0))[1];

#pragma unroll
    for (int d = 0; d < 4; d++) {
        float sE, sO, qE, qO;
        unpack2(sum2[d], sE, sO);
        unpack2(sq2[d], qE, qO);
        float mE = sE * (1.0f / DD), mO = sO * (1.0f / DD);
        float rE = rsqrtf(qE * (1.0f / DD) - mE * mE + 1e-5f);
        float rO = rsqrtf(qO * (1.0f / DD) - mO * mO + 1e-5f);

        float xe[8], xo[8];
#pragma unroll
        for (int oo = 0; oo < 8; oo++) unpack2(acc[d][oo], xe[oo], xo[oo]);

        const int sA = s0 + 8 * sg + 2 * d;
        float* rowE = out + ((long)(b * SS + sA)) * DD + o0;
        float* rowO = rowE + DD;
        float4 r;
        r.x = (xe[0] - mE) * rE * g0.x + e0.x;
        r.y = (xe[1] - mE) * rE * g0.y + e0.y;
        r.z = (xe[2] - mE) * rE * g0.z + e0.z;
        r.w = (xe[3] - mE) * rE * g0.w + e0.w;
        *(float4*)rowE = r;
        r.x = (xe[4] - mE) * rE * g1.x + e1.x;
        r.y = (xe[5] - mE) * rE * g1.y + e1.y;
        r.z = (xe[6] - mE) * rE * g1.z + e1.z;
        r.w = (xe[7] - mE) * rE * g1.w + e1.w;
        *(float4*)(rowE + 4) = r;
        r.x = (xo[0] - mO) * rO * g0.x + e0.x;
        r.y = (xo[1] - mO) * rO * g0.y + e0.y;
        r.z = (xo[2] - mO) * rO * g0.z + e0.z;
        r.w = (xo[3] - mO) * rO * g0.w + e0.w;
        *(float4*)rowO = r;
        r.x = (xo[4] - mO) * rO * g1.x + e1.x;
        r.y = (xo[5] - mO) * rO * g1.y + e1.y;
        r.z = (xo[6] - mO) * rO * g1.z + e1.z;
        r.w = (xo[7] - mO) * rO * g1.w + e1.w;
        *(float4*)(rowO + 4) = r;
    }
}

extern "C" void kernel_launch(void* const* d_in, const int* in_sizes, int n_in,
                              void* d_out, int out_size) {
    const int* seq = (const int*)d_in[0];
    const int* kid = (const int*)d_in[1];
    const float* emb = (const float*)d_in[2];
    const float* ktab = (const float*)d_in[3];
    const float* W = (const float*)d_in[4];
    const float* bias = (const float*)d_in[5];
    const float* gamma = (const float*)d_in[6];
    const float* beta = (const float*)d_in[7];
    float* out = (float*)d_out;

    k1_project<<<256, 128>>>(W, ktab, kid);
    k2_gemm_ln<<<NB * (SS / STILE), 256>>>(emb, seq, kid, bias, gamma, beta, out);
}